// round 11
// baseline (speedup 1.0000x reference)
#include <cuda_runtime.h>
#include <cuda_bf16.h>
#include <math_constants.h>

// Problem dims
#define Bn   8
#define An   64
#define Ln   30
#define Dn   128
#define Kn   16
#define Mn   128
#define Hn   8
#define HDn  16
#define NROWS (Bn*An*Ln)           // 15360
#define JTOT (Kn*Ln)               // 480
#define SCP  481                   // padded score stride
#define SCALE 0.25f
#define HSTRIDE 480                // floats per (ba,h) block in head-major layout
#define BASTRIDE 3840              // floats per ba block (8 heads)

// ---- packed f32x2 helpers (Blackwell FFMA2 path) ---------------------------
typedef unsigned long long u64;
union F4U2 { float4 f; u64 u[2]; };

__device__ __forceinline__ u64 pack2(float lo, float hi) {
    u64 r; asm("mov.b64 %0, {%1,%2};" : "=l"(r) : "f"(lo), "f"(hi)); return r;
}
__device__ __forceinline__ void unpack2(u64 v, float& lo, float& hi) {
    asm("mov.b64 {%0,%1}, %2;" : "=f"(lo), "=f"(hi) : "l"(v));
}
__device__ __forceinline__ u64 fma2(u64 a, u64 b, u64 c) {
    u64 d; asm("fma.rn.f32x2 %0, %1, %2, %3;" : "=l"(d) : "l"(a), "l"(b), "l"(c)); return d;
}

// Scratch (device globals; no allocation allowed)
// Q/K/V/ctx stored HEAD-MAJOR: [ba(512)][h(8)][l(30)][hd(16)]
__device__ float g_q[NROWS*Mn];
__device__ float g_k[NROWS*Mn];
__device__ float g_v[NROWS*Mn];
__device__ float g_ctx[NROWS*Mn];
__device__ int   g_mask_mode;      // 0 = u8/bool, 1 = int32, 2 = float32

// ---------------------------------------------------------------------------
__global__ void __launch_bounds__(256) detect_mask_kernel(const unsigned int* __restrict__ m)
{
    __shared__ int s_f32, s_hi;
    if (threadIdx.x == 0) { s_f32 = 0; s_hi = 0; }
    __syncthreads();
    int f32 = 0, hi = 0;
#pragma unroll
    for (int i = 0; i < 8; i++) {
        unsigned int w = m[threadIdx.x + 256*i];
        f32 |= (w == 0x3f800000u);
        hi  |= ((w & 0xFFFFFF00u) != 0u);
    }
    if (f32) s_f32 = 1;
    if (hi)  s_hi  = 1;
    __syncthreads();
    if (threadIdx.x == 0)
        g_mask_mode = s_f32 ? 2 : (s_hi ? 0 : 1);
}

__global__ void noop_kernel() {}

// ---------------------------------------------------------------------------
// GEMM core: 32x128 CTA tile; X staged in smem (16.5KB); W via coalesced LDG.
// Thread owns 2 rows (ty, ty+16) x 8 consecutive cols -> 8 u64 acc.
// ---------------------------------------------------------------------------
__device__ __forceinline__ void gemm_compute32(
    const float* __restrict__ W, const float* Xs, int tid, u64 acc[2][4])
{
    const int tx = tid & 15;
    const int ty = tid >> 4;
#pragma unroll
    for (int i = 0; i < 2; i++)
#pragma unroll
        for (int j = 0; j < 4; j++) acc[i][j] = 0ULL;

    const float4* Wg = reinterpret_cast<const float4*>(W);
#pragma unroll 8
    for (int k = 0; k < 128; k++) {
        float a0 = Xs[ty*129 + k];
        float a1 = Xs[(ty+16)*129 + k];
        u64 aa0 = pack2(a0, a0);
        u64 aa1 = pack2(a1, a1);
        F4U2 b0, b1;
        b0.f = __ldg(&Wg[k*32 + tx*2 + 0]);
        b1.f = __ldg(&Wg[k*32 + tx*2 + 1]);
        u64 bb[4] = {b0.u[0], b0.u[1], b1.u[0], b1.u[1]};
#pragma unroll
        for (int j = 0; j < 4; j++) {
            acc[0][j] = fma2(aa0, bb[j], acc[0][j]);
            acc[1][j] = fma2(aa1, bb[j], acc[1][j]);
        }
    }
}

// QKV GEMM: X = future_feat (row-major [15360,128]); writes HEAD-MAJOR.
__global__ void __launch_bounds__(256, 4) gemm_qkv_kernel(
    const float* __restrict__ X,
    const float* __restrict__ Wq, const float* __restrict__ bq, float* __restrict__ Cq,
    const float* __restrict__ Wk, const float* __restrict__ bk, float* __restrict__ Ck,
    const float* __restrict__ Wv, const float* __restrict__ bv, float* __restrict__ Cv)
{
    const float* W; const float* bias; float* C;
    if (blockIdx.y == 0)      { W = Wq; bias = bq; C = Cq; }
    else if (blockIdx.y == 1) { W = Wk; bias = bk; C = Ck; }
    else                      { W = Wv; bias = bv; C = Cv; }

    extern __shared__ float sm[];
    float* Xs = sm;                 // 32 x 129
    const int tid  = threadIdx.x;
    const int row0 = blockIdx.x * 32;

    const float4* Xg = reinterpret_cast<const float4*>(X + (size_t)row0 * 128);
#pragma unroll
    for (int i = 0; i < 4; i++) {
        int idx = tid + 256*i;          // 1024 float4
        float4 v = Xg[idx];
        int r = idx >> 5;
        int c = (idx & 31) * 4;
        Xs[r*129 + c + 0] = v.x;
        Xs[r*129 + c + 1] = v.y;
        Xs[r*129 + c + 2] = v.z;
        Xs[r*129 + c + 3] = v.w;
    }
    __syncthreads();

    u64 acc[2][4];
    gemm_compute32(W, Xs, tid, acc);

    const int tx = tid & 15;
    const int ty = tid >> 4;
    const float4* bias4 = reinterpret_cast<const float4*>(bias);
    float4 bb0 = bias4[tx*2 + 0];
    float4 bb1 = bias4[tx*2 + 1];
    float bb[8] = {bb0.x, bb0.y, bb0.z, bb0.w, bb1.x, bb1.y, bb1.z, bb1.w};
    const int h   = tx >> 1;
    const int hd0 = (tx & 1) * 8;
#pragma unroll
    for (int i = 0; i < 2; i++) {
        int r  = row0 + ty + 16*i;      // global row = ba*30 + l
        int ba = r / Ln;
        int l  = r - ba*Ln;
        float av[8];
#pragma unroll
        for (int j = 0; j < 4; j++) unpack2(acc[i][j], av[j*2], av[j*2+1]);
        float4* dst = reinterpret_cast<float4*>(C + (size_t)ba*BASTRIDE + h*HSTRIDE + l*HDn + hd0);
        dst[0] = make_float4(av[0]+bb[0], av[1]+bb[1], av[2]+bb[2], av[3]+bb[3]);
        dst[1] = make_float4(av[4]+bb[4], av[5]+bb[5], av[6]+bb[6], av[7]+bb[7]);
    }
}

// Output GEMM: X = ctx in HEAD-MAJOR; gathers into smem; writes row-major out.
__global__ void __launch_bounds__(256, 4) gemm_out_kernel(
    const float* __restrict__ Xhm, const float* __restrict__ W,
    const float* __restrict__ bias, float* __restrict__ C)
{
    extern __shared__ float sm[];
    float* Xs = sm;                 // 32 x 129
    const int tid  = threadIdx.x;
    const int row0 = blockIdx.x * 32;

#pragma unroll
    for (int i = 0; i < 4; i++) {
        int idx = tid + 256*i;          // 1024 float4
        int r  = idx >> 5;
        int c4 = idx & 31;
        int g  = row0 + r;              // global row = ba*30 + l
        int ba = g / Ln;
        int l  = g - ba*Ln;
        int h  = c4 >> 2;
        int hd = (c4 & 3) * 4;
        float4 v = *reinterpret_cast<const float4*>(
            Xhm + (size_t)ba*BASTRIDE + h*HSTRIDE + l*HDn + hd);
        int c = c4 * 4;
        Xs[r*129 + c + 0] = v.x;
        Xs[r*129 + c + 1] = v.y;
        Xs[r*129 + c + 2] = v.z;
        Xs[r*129 + c + 3] = v.w;
    }
    __syncthreads();

    u64 acc[2][4];
    gemm_compute32(W, Xs, tid, acc);

    const int tx = tid & 15;
    const int ty = tid >> 4;
    const float4* bias4 = reinterpret_cast<const float4*>(bias);
    float4 bb0 = bias4[tx*2 + 0];
    float4 bb1 = bias4[tx*2 + 1];
    float bb[8] = {bb0.x, bb0.y, bb0.z, bb0.w, bb1.x, bb1.y, bb1.z, bb1.w};
#pragma unroll
    for (int i = 0; i < 2; i++) {
        int r = row0 + ty + 16*i;
        float av[8];
#pragma unroll
        for (int j = 0; j < 4; j++) unpack2(acc[i][j], av[j*2], av[j*2+1]);
        float4* dst = reinterpret_cast<float4*>(C + (size_t)r*128 + tx*8);
        dst[0] = make_float4(av[0]+bb[0], av[1]+bb[1], av[2]+bb[2], av[3]+bb[3]);
        dst[1] = make_float4(av[4]+bb[4], av[5]+bb[5], av[6]+bb[6], av[7]+bb[7]);
    }
}

// ---------------------------------------------------------------------------
// Attention: one 480-thread CTA per (b, a, h); 2 CTAs/SM (30 warps).
// Thread owns exactly ONE j row. Head-major Q/K/V.
// smem: qs[480] | sc[30*481] = 59640 B
// ---------------------------------------------------------------------------
__global__ void __launch_bounds__(480, 2) attn_kernel(
    const float* __restrict__ gq, const float* __restrict__ gk,
    const float* __restrict__ gv, const float* __restrict__ geom_bias,
    const int* __restrict__ nidx, const void* __restrict__ nmask,
    float* __restrict__ attn_out, float* __restrict__ ctx_out)
{
    const int bid = blockIdx.x;
    const int h  = bid & 7;
    const int a  = (bid >> 3) & 63;
    const int b  = bid >> 9;
    const int ba = b*An + a;
    const int tid  = threadIdx.x;
    const int warp = tid >> 5;
    const int lane = tid & 31;

    extern __shared__ float sm[];
    float* qs = sm;                    // 480 floats
    float* sc = qs + Ln*HDn;           // 30*481 (scores -> partials)

    __shared__ int   rowbase[Kn];      // head-major base (floats) per neighbour
    __shared__ float biasS[Kn];
    __shared__ int   maskS[Kn];

    if (tid < Kn) {
        int n = nidx[ba*Kn + tid];
        rowbase[tid] = ((b*An + n)*Hn + h) * HSTRIDE;
        biasS[tid]   = geom_bias[ba*Kn + tid];
        int mode = g_mask_mode;
        bool mv;
        if (mode == 0)      mv = ((const unsigned char*)nmask)[ba*Kn + tid] != 0;
        else if (mode == 1) mv = ((const int*)nmask)[ba*Kn + tid] != 0;
        else                mv = ((const float*)nmask)[ba*Kn + tid] != 0.0f;
        maskS[tid] = mv ? 1 : 0;
    }
    // q head slice: contiguous 480 floats = 120 float4
    if (tid < Ln*4) {
        const float4* qbase = reinterpret_cast<const float4*>(gq + (size_t)(ba*Hn + h)*HSTRIDE);
        reinterpret_cast<float4*>(qs)[tid] = qbase[tid];
    }
    __syncthreads();   // rowbase + qs ready

    // K row straight from global into PACKED registers: thread owns j = tid
    const int j0  = tid;
    const int kk0 = j0 / Ln;
    const int l0  = j0 - kk0*Ln;
    u64 k0[8];
    {
        const float4* src0 = reinterpret_cast<const float4*>(gk + rowbase[kk0] + l0*HDn);
        F4U2 t;
#pragma unroll
        for (int c = 0; c < 4; c++) {
            t.f = src0[c];
            k0[c*2+0] = t.u[0]; k0[c*2+1] = t.u[1];
        }
    }
    const float bias0 = biasS[kk0];
    const bool  m0 = maskS[kk0] != 0;

    // scores (q pairs, packed FFMA2)
    const float NEGINF = -CUDART_INF_F;
    const float4* qs4 = reinterpret_cast<const float4*>(qs);
#pragma unroll 1
    for (int qp = 0; qp < Ln/2; qp++) {
        int q0 = qp * 2;
        u64 qa[8], qb[8];
        {
            F4U2 t;
#pragma unroll
            for (int c = 0; c < 4; c++) {
                t.f = qs4[q0*4 + c];
                qa[c*2+0] = t.u[0]; qa[c*2+1] = t.u[1];
            }
#pragma unroll
            for (int c = 0; c < 4; c++) {
                t.f = qs4[(q0+1)*4 + c];
                qb[c*2+0] = t.u[0]; qb[c*2+1] = t.u[1];
            }
        }
        u64 p00 = 0ULL, p10 = 0ULL;
#pragma unroll
        for (int d = 0; d < 8; d++) {
            p00 = fma2(qa[d], k0[d], p00);
            p10 = fma2(qb[d], k0[d], p10);
        }
        float lo, hi;
        unpack2(p00, lo, hi); float s00 = lo + hi;
        unpack2(p10, lo, hi); float s10 = lo + hi;
        sc[q0*SCP + j0]     = m0 ? fmaf(s00, SCALE, bias0) : NEGINF;
        sc[(q0+1)*SCP + j0] = m0 ? fmaf(s10, SCALE, bias0) : NEGINF;
    }
    __syncthreads();

    // softmax: 15 warps, each owns rows {warp, warp+15}; 15 elems/lane in regs
#pragma unroll
    for (int rr = 0; rr < 2; rr++) {
        int q = warp + rr*15;
        float* row = sc + q*SCP;
        float* arow = attn_out + ((size_t)(ba*Hn + h)*Ln + q) * JTOT;
        float p[15];
#pragma unroll
        for (int i = 0; i < 15; i++) p[i] = row[i*32 + lane];
        float m = p[0];
#pragma unroll
        for (int i = 1; i < 15; i++) m = fmaxf(m, p[i]);
#pragma unroll
        for (int off = 16; off; off >>= 1) m = fmaxf(m, __shfl_xor_sync(0xffffffffu, m, off));
        if (m == NEGINF) {
#pragma unroll
            for (int i = 0; i < 15; i++) { row[i*32 + lane] = 0.f; arow[i*32 + lane] = 0.f; }
        } else {
            float s = 0.f;
#pragma unroll
            for (int i = 0; i < 15; i++) { p[i] = __expf(p[i] - m); s += p[i]; }
#pragma unroll
            for (int off = 16; off; off >>= 1) s += __shfl_xor_sync(0xffffffffu, s, off);
            float inv = 1.f / s;
#pragma unroll
            for (int i = 0; i < 15; i++) {
                float v = p[i] * inv;
                row[i*32 + lane] = v;
                arow[i*32 + lane] = v;
            }
        }
    }
    __syncthreads();

    // P @ V : warp w owns j in [32w, 32w+32); lane = q row (30 active).
    // V broadcast-LDG from contiguous head-major rows; unrolled for MLP.
    u64 acc[8];
#pragma unroll
    for (int d = 0; d < 8; d++) acc[d] = 0ULL;
    if (lane < Ln) {
        const float* prow = sc + lane*SCP;
        const int jlo = warp*32;
#pragma unroll 4
        for (int j = jlo; j < jlo + 32; j++) {
            int kk = j / Ln;
            const float4* src = reinterpret_cast<const float4*>(gv + rowbase[kk] + (j - kk*Ln)*HDn);
            float p = prow[j];
            u64 pp = pack2(p, p);
            F4U2 v0, v1, v2, v3;
            v0.f = src[0]; v1.f = src[1]; v2.f = src[2]; v3.f = src[3];
            acc[0] = fma2(pp, v0.u[0], acc[0]); acc[1] = fma2(pp, v0.u[1], acc[1]);
            acc[2] = fma2(pp, v1.u[0], acc[2]); acc[3] = fma2(pp, v1.u[1], acc[3]);
            acc[4] = fma2(pp, v2.u[0], acc[4]); acc[5] = fma2(pp, v2.u[1], acc[5]);
            acc[6] = fma2(pp, v3.u[0], acc[6]); acc[7] = fma2(pp, v3.u[1], acc[7]);
        }
    }
    __syncthreads();   // sc reads done; region reusable for partials
    if (lane < Ln) {
        float av[16];
#pragma unroll
        for (int d = 0; d < 8; d++) unpack2(acc[d], av[2*d], av[2*d+1]);
        float4* dst = reinterpret_cast<float4*>(sc + warp*480 + lane*HDn);
#pragma unroll
        for (int c = 0; c < 4; c++)
            dst[c] = make_float4(av[c*4+0], av[c*4+1], av[c*4+2], av[c*4+3]);
    }
    __syncthreads();

    // reduce 15 partials, write ctx HEAD-MAJOR (contiguous 480 floats)
    if (tid < Ln*HDn) {
        float s = 0.f;
#pragma unroll
        for (int ww = 0; ww < 15; ww++) s += sc[ww*480 + tid];
        ctx_out[(size_t)(ba*Hn + h)*HSTRIDE + tid] = s;
    }
}

// ---------------------------------------------------------------------------
extern "C" void kernel_launch(void* const* d_in, const int* in_sizes, int n_in,
                              void* d_out, int out_size)
{
    const float* ff   = (const float*)d_in[0];
    const float* gb   = (const float*)d_in[1];
    const float* Wq   = (const float*)d_in[2];
    const float* bq   = (const float*)d_in[3];
    const float* Wk   = (const float*)d_in[4];
    const float* bk   = (const float*)d_in[5];
    const float* Wv   = (const float*)d_in[6];
    const float* bv   = (const float*)d_in[7];
    const float* Wo   = (const float*)d_in[8];
    const float* bo   = (const float*)d_in[9];
    const int*   nidx = (const int*)d_in[10];
    const void*  nmask = (const void*)d_in[11];

    float* out  = (float*)d_out;
    float* attn = out + (size_t)Bn*An*Ln*Mn;

    float *pq, *pk, *pv, *pctx;
    cudaGetSymbolAddress((void**)&pq,  g_q);
    cudaGetSymbolAddress((void**)&pk,  g_k);
    cudaGetSymbolAddress((void**)&pv,  g_v);
    cudaGetSymbolAddress((void**)&pctx, g_ctx);

    const int gemm_smem = 32*129*4;                        // 16512 B
    const int attn_smem = (Ln*HDn + Ln*SCP) * 4;           // 59640 B
    cudaFuncSetAttribute(gemm_qkv_kernel, cudaFuncAttributeMaxDynamicSharedMemorySize, gemm_smem);
    cudaFuncSetAttribute(gemm_out_kernel, cudaFuncAttributeMaxDynamicSharedMemorySize, gemm_smem);
    cudaFuncSetAttribute(attn_kernel,     cudaFuncAttributeMaxDynamicSharedMemorySize, attn_smem);

    // launch #1: mask dtype detection
    detect_mask_kernel<<<1, 256>>>((const unsigned int*)nmask);

    // launch #2: fused QKV projections (head-major outputs), 1440 CTAs
    dim3 gqkv(NROWS/32, 3);
    gemm_qkv_kernel<<<gqkv, 256, gemm_smem>>>(ff, Wq, bq, pq, Wk, bk, pk, Wv, bv, pv);

    // launch #3: alignment noop (profiled launch is #4 — put attn there)
    noop_kernel<<<1, 32>>>();

    // launch #4: attention, single launch (4096 CTAs x 480 threads)
    attn_kernel<<<Bn*An*Hn, 480, attn_smem>>>(pq, pk, pv, gb, nidx, nmask, attn, pctx);

    // launch #5: output projection (480 CTAs)
    gemm_out_kernel<<<NROWS/32, 256, gemm_smem>>>(pctx, Wo, bo, out);
}

// round 12
// speedup vs baseline: 1.1115x; 1.1115x over previous
#include <cuda_runtime.h>
#include <cuda_bf16.h>
#include <math_constants.h>

// Problem dims
#define Bn   8
#define An   64
#define Ln   30
#define Dn   128
#define Kn   16
#define Mn   128
#define Hn   8
#define HDn  16
#define NROWS (Bn*An*Ln)           // 15360
#define JTOT (Kn*Ln)               // 480
#define SCP  481                   // padded score stride
#define SCALE 0.25f
#define HSTRIDE 480                // floats per (ba,h) block in head-major layout
#define BASTRIDE 3840              // floats per ba block (8 heads)

// ---- packed f32x2 helpers (Blackwell FFMA2 path) ---------------------------
typedef unsigned long long u64;
union F4U2 { float4 f; u64 u[2]; };

__device__ __forceinline__ u64 pack2(float lo, float hi) {
    u64 r; asm("mov.b64 %0, {%1,%2};" : "=l"(r) : "f"(lo), "f"(hi)); return r;
}
__device__ __forceinline__ void unpack2(u64 v, float& lo, float& hi) {
    asm("mov.b64 {%0,%1}, %2;" : "=f"(lo), "=f"(hi) : "l"(v));
}
__device__ __forceinline__ u64 fma2(u64 a, u64 b, u64 c) {
    u64 d; asm("fma.rn.f32x2 %0, %1, %2, %3;" : "=l"(d) : "l"(a), "l"(b), "l"(c)); return d;
}

// Scratch (device globals; no allocation allowed)
// Q/K/V/ctx stored HEAD-MAJOR: [ba(512)][h(8)][l(30)][hd(16)]
__device__ float g_q[NROWS*Mn];
__device__ float g_k[NROWS*Mn];
__device__ float g_v[NROWS*Mn];
__device__ float g_ctx[NROWS*Mn];
__device__ int   g_mask_mode;      // 0 = u8/bool, 1 = int32, 2 = float32

// ---------------------------------------------------------------------------
__global__ void __launch_bounds__(256) detect_mask_kernel(const unsigned int* __restrict__ m)
{
    __shared__ int s_f32, s_hi;
    if (threadIdx.x == 0) { s_f32 = 0; s_hi = 0; }
    __syncthreads();
    int f32 = 0, hi = 0;
#pragma unroll
    for (int i = 0; i < 8; i++) {
        unsigned int w = m[threadIdx.x + 256*i];
        f32 |= (w == 0x3f800000u);
        hi  |= ((w & 0xFFFFFF00u) != 0u);
    }
    if (f32) s_f32 = 1;
    if (hi)  s_hi  = 1;
    __syncthreads();
    if (threadIdx.x == 0)
        g_mask_mode = s_f32 ? 2 : (s_hi ? 0 : 1);
}

__global__ void noop_kernel() {}

// ---------------------------------------------------------------------------
// GEMM core: 64x128 CTA tile, 512 threads; thread owns 2 rows x 8 cols.
// X staged in smem (33KB); W via coalesced LDG (L1-resident after 1st pass).
// ---------------------------------------------------------------------------
__device__ __forceinline__ void gemm_compute64x512(
    const float* __restrict__ W, const float* Xs, int tid, u64 acc[2][4])
{
    const int tx = tid & 15;        // col block: cols tx*8 .. tx*8+7
    const int ty = tid >> 4;        // 0..31: rows ty, ty+32
#pragma unroll
    for (int i = 0; i < 2; i++)
#pragma unroll
        for (int j = 0; j < 4; j++) acc[i][j] = 0ULL;

    const float4* Wg = reinterpret_cast<const float4*>(W);
#pragma unroll 8
    for (int k = 0; k < 128; k++) {
        float a0 = Xs[ty*129 + k];
        float a1 = Xs[(ty+32)*129 + k];
        u64 aa0 = pack2(a0, a0);
        u64 aa1 = pack2(a1, a1);
        F4U2 b0, b1;
        b0.f = __ldg(&Wg[k*32 + tx*2 + 0]);
        b1.f = __ldg(&Wg[k*32 + tx*2 + 1]);
        u64 bb[4] = {b0.u[0], b0.u[1], b1.u[0], b1.u[1]};
#pragma unroll
        for (int j = 0; j < 4; j++) {
            acc[0][j] = fma2(aa0, bb[j], acc[0][j]);
            acc[1][j] = fma2(aa1, bb[j], acc[1][j]);
        }
    }
}

// QKV GEMM: X = future_feat (row-major [15360,128]); writes HEAD-MAJOR.
__global__ void __launch_bounds__(512, 2) gemm_qkv_kernel(
    const float* __restrict__ X,
    const float* __restrict__ Wq, const float* __restrict__ bq, float* __restrict__ Cq,
    const float* __restrict__ Wk, const float* __restrict__ bk, float* __restrict__ Ck,
    const float* __restrict__ Wv, const float* __restrict__ bv, float* __restrict__ Cv)
{
    const float* W; const float* bias; float* C;
    if (blockIdx.y == 0)      { W = Wq; bias = bq; C = Cq; }
    else if (blockIdx.y == 1) { W = Wk; bias = bk; C = Ck; }
    else                      { W = Wv; bias = bv; C = Cv; }

    extern __shared__ float sm[];
    float* Xs = sm;                 // 64 x 129
    const int tid  = threadIdx.x;
    const int row0 = blockIdx.x * 64;

    const float4* Xg = reinterpret_cast<const float4*>(X + (size_t)row0 * 128);
#pragma unroll
    for (int i = 0; i < 4; i++) {
        int idx = tid + 512*i;          // 2048 float4
        float4 v = Xg[idx];
        int r = idx >> 5;
        int c = (idx & 31) * 4;
        Xs[r*129 + c + 0] = v.x;
        Xs[r*129 + c + 1] = v.y;
        Xs[r*129 + c + 2] = v.z;
        Xs[r*129 + c + 3] = v.w;
    }
    __syncthreads();

    u64 acc[2][4];
    gemm_compute64x512(W, Xs, tid, acc);

    const int tx = tid & 15;
    const int ty = tid >> 4;
    const float4* bias4 = reinterpret_cast<const float4*>(bias);
    float4 bb0 = bias4[tx*2 + 0];
    float4 bb1 = bias4[tx*2 + 1];
    float bb[8] = {bb0.x, bb0.y, bb0.z, bb0.w, bb1.x, bb1.y, bb1.z, bb1.w};
    const int h   = tx >> 1;
    const int hd0 = (tx & 1) * 8;
#pragma unroll
    for (int i = 0; i < 2; i++) {
        int r  = row0 + ty + 32*i;      // global row = ba*30 + l
        int ba = r / Ln;
        int l  = r - ba*Ln;
        float av[8];
#pragma unroll
        for (int j = 0; j < 4; j++) unpack2(acc[i][j], av[j*2], av[j*2+1]);
        float4* dst = reinterpret_cast<float4*>(C + (size_t)ba*BASTRIDE + h*HSTRIDE + l*HDn + hd0);
        dst[0] = make_float4(av[0]+bb[0], av[1]+bb[1], av[2]+bb[2], av[3]+bb[3]);
        dst[1] = make_float4(av[4]+bb[4], av[5]+bb[5], av[6]+bb[6], av[7]+bb[7]);
    }
}

// Output GEMM: X = ctx in HEAD-MAJOR; gathers into smem; writes row-major out.
__global__ void __launch_bounds__(512, 2) gemm_out_kernel(
    const float* __restrict__ Xhm, const float* __restrict__ W,
    const float* __restrict__ bias, float* __restrict__ C)
{
    extern __shared__ float sm[];
    float* Xs = sm;                 // 64 x 129
    const int tid  = threadIdx.x;
    const int row0 = blockIdx.x * 64;

#pragma unroll
    for (int i = 0; i < 4; i++) {
        int idx = tid + 512*i;          // 2048 float4
        int r  = idx >> 5;
        int c4 = idx & 31;
        int g  = row0 + r;              // global row = ba*30 + l
        int ba = g / Ln;
        int l  = g - ba*Ln;
        int h  = c4 >> 2;
        int hd = (c4 & 3) * 4;
        float4 v = *reinterpret_cast<const float4*>(
            Xhm + (size_t)ba*BASTRIDE + h*HSTRIDE + l*HDn + hd);
        int c = c4 * 4;
        Xs[r*129 + c + 0] = v.x;
        Xs[r*129 + c + 1] = v.y;
        Xs[r*129 + c + 2] = v.z;
        Xs[r*129 + c + 3] = v.w;
    }
    __syncthreads();

    u64 acc[2][4];
    gemm_compute64x512(W, Xs, tid, acc);

    const int tx = tid & 15;
    const int ty = tid >> 4;
    const float4* bias4 = reinterpret_cast<const float4*>(bias);
    float4 bb0 = bias4[tx*2 + 0];
    float4 bb1 = bias4[tx*2 + 1];
    float bb[8] = {bb0.x, bb0.y, bb0.z, bb0.w, bb1.x, bb1.y, bb1.z, bb1.w};
#pragma unroll
    for (int i = 0; i < 2; i++) {
        int r = row0 + ty + 32*i;
        float av[8];
#pragma unroll
        for (int j = 0; j < 4; j++) unpack2(acc[i][j], av[j*2], av[j*2+1]);
        float4* dst = reinterpret_cast<float4*>(C + (size_t)r*128 + tx*8);
        dst[0] = make_float4(av[0]+bb[0], av[1]+bb[1], av[2]+bb[2], av[3]+bb[3]);
        dst[1] = make_float4(av[4]+bb[4], av[5]+bb[5], av[6]+bb[6], av[7]+bb[7]);
    }
}

// ---------------------------------------------------------------------------
// Attention (R10 configuration — best measured): one 256-thread CTA per
// (b,a,h); 3 CTAs/SM. Head-major Q/K/V; K global->regs; V broadcast-LDG.
// smem: qs[480] | sc[30*481] = 59640 B
// ---------------------------------------------------------------------------
__global__ void __launch_bounds__(256, 3) attn_kernel(
    const float* __restrict__ gq, const float* __restrict__ gk,
    const float* __restrict__ gv, const float* __restrict__ geom_bias,
    const int* __restrict__ nidx, const void* __restrict__ nmask,
    float* __restrict__ attn_out, float* __restrict__ ctx_out)
{
    const int bid = blockIdx.x;
    const int h  = bid & 7;
    const int a  = (bid >> 3) & 63;
    const int b  = bid >> 9;
    const int ba = b*An + a;
    const int tid = threadIdx.x;

    extern __shared__ float sm[];
    float* qs = sm;                    // 480 floats
    float* sc = qs + Ln*HDn;           // 30*481 (scores -> partials)

    __shared__ int   rowbase[Kn];      // head-major base (floats) per neighbour
    __shared__ float biasS[Kn];
    __shared__ int   maskS[Kn];

    if (tid < Kn) {
        int n = nidx[ba*Kn + tid];
        rowbase[tid] = ((b*An + n)*Hn + h) * HSTRIDE;
        biasS[tid]   = geom_bias[ba*Kn + tid];
        int mode = g_mask_mode;
        bool mv;
        if (mode == 0)      mv = ((const unsigned char*)nmask)[ba*Kn + tid] != 0;
        else if (mode == 1) mv = ((const int*)nmask)[ba*Kn + tid] != 0;
        else                mv = ((const float*)nmask)[ba*Kn + tid] != 0.0f;
        maskS[tid] = mv ? 1 : 0;
    }
    // q head slice: contiguous 480 floats = 120 float4
    if (tid < Ln*4) {
        const float4* qbase = reinterpret_cast<const float4*>(gq + (size_t)(ba*Hn + h)*HSTRIDE);
        reinterpret_cast<float4*>(qs)[tid] = qbase[tid];
    }
    __syncthreads();   // rowbase + qs ready

    // K rows straight from global into PACKED registers
    const int j0 = tid;
    const int j1 = tid + 256;
    const bool hasJ1 = (tid < JTOT - 256);   // tid < 224
    const int kk0 = j0 / Ln;
    const int l0  = j0 - kk0*Ln;
    const int kk1 = j1 / Ln;
    const int l1  = j1 - kk1*Ln;
    u64 k0[8], k1[8];
    {
        const float4* src0 = reinterpret_cast<const float4*>(gk + rowbase[kk0] + l0*HDn);
        F4U2 t;
#pragma unroll
        for (int c = 0; c < 4; c++) {
            t.f = src0[c];
            k0[c*2+0] = t.u[0]; k0[c*2+1] = t.u[1];
        }
        if (hasJ1) {
            const float4* src1 = reinterpret_cast<const float4*>(gk + rowbase[kk1] + l1*HDn);
#pragma unroll
            for (int c = 0; c < 4; c++) {
                t.f = src1[c];
                k1[c*2+0] = t.u[0]; k1[c*2+1] = t.u[1];
            }
        }
    }
    const float bias0 = biasS[kk0];
    const bool  m0 = maskS[kk0] != 0;
    const float bias1 = hasJ1 ? biasS[kk1] : 0.f;
    const bool  m1 = hasJ1 ? (maskS[kk1] != 0) : false;

    // scores from packed register K
    const float NEGINF = -CUDART_INF_F;
    const float4* qs4 = reinterpret_cast<const float4*>(qs);
#pragma unroll 1
    for (int qp = 0; qp < Ln/2; qp++) {
        int q0 = qp * 2;
        u64 qa[8], qb[8];
        {
            F4U2 t;
#pragma unroll
            for (int c = 0; c < 4; c++) {
                t.f = qs4[q0*4 + c];
                qa[c*2+0] = t.u[0]; qa[c*2+1] = t.u[1];
            }
#pragma unroll
            for (int c = 0; c < 4; c++) {
                t.f = qs4[(q0+1)*4 + c];
                qb[c*2+0] = t.u[0]; qb[c*2+1] = t.u[1];
            }
        }
        u64 p00 = 0ULL, p10 = 0ULL, p01 = 0ULL, p11 = 0ULL;
#pragma unroll
        for (int d = 0; d < 8; d++) {
            p00 = fma2(qa[d], k0[d], p00);
            p10 = fma2(qb[d], k0[d], p10);
        }
        if (hasJ1) {
#pragma unroll
            for (int d = 0; d < 8; d++) {
                p01 = fma2(qa[d], k1[d], p01);
                p11 = fma2(qb[d], k1[d], p11);
            }
        }
        float lo, hi;
        unpack2(p00, lo, hi); float s00 = lo + hi;
        unpack2(p10, lo, hi); float s10 = lo + hi;
        sc[q0*SCP + j0]     = m0 ? fmaf(s00, SCALE, bias0) : NEGINF;
        sc[(q0+1)*SCP + j0] = m0 ? fmaf(s10, SCALE, bias0) : NEGINF;
        if (hasJ1) {
            unpack2(p01, lo, hi); float s01 = lo + hi;
            unpack2(p11, lo, hi); float s11 = lo + hi;
            sc[q0*SCP + j1]     = m1 ? fmaf(s01, SCALE, bias1) : NEGINF;
            sc[(q0+1)*SCP + j1] = m1 ? fmaf(s11, SCALE, bias1) : NEGINF;
        }
    }
    __syncthreads();

    // softmax: one warp per row, 15 elements per lane held in registers
    {
        const int warp = tid >> 5, lane = tid & 31;
        for (int q = warp; q < Ln; q += 8) {
            float* row = sc + q*SCP;
            float* arow = attn_out + ((size_t)(ba*Hn + h)*Ln + q) * JTOT;
            float p[15];
#pragma unroll
            for (int i = 0; i < 15; i++) p[i] = row[i*32 + lane];
            float m = p[0];
#pragma unroll
            for (int i = 1; i < 15; i++) m = fmaxf(m, p[i]);
#pragma unroll
            for (int off = 16; off; off >>= 1) m = fmaxf(m, __shfl_xor_sync(0xffffffffu, m, off));
            if (m == NEGINF) {
#pragma unroll
                for (int i = 0; i < 15; i++) { row[i*32 + lane] = 0.f; arow[i*32 + lane] = 0.f; }
            } else {
                float s = 0.f;
#pragma unroll
                for (int i = 0; i < 15; i++) { p[i] = __expf(p[i] - m); s += p[i]; }
#pragma unroll
                for (int off = 16; off; off >>= 1) s += __shfl_xor_sync(0xffffffffu, s, off);
                float inv = 1.f / s;
#pragma unroll
                for (int i = 0; i < 15; i++) {
                    float v = p[i] * inv;
                    row[i*32 + lane] = v;
                    arow[i*32 + lane] = v;
                }
            }
        }
    }
    __syncthreads();

    // P @ V : warp w owns kk = 2w, 2w+1; lane = q row (30 active).
    const int w    = tid >> 5;
    const int lane = tid & 31;
    u64 acc[8];
#pragma unroll
    for (int d = 0; d < 8; d++) acc[d] = 0ULL;
    if (lane < Ln) {
        const float* prow = sc + lane*SCP;
#pragma unroll
        for (int half = 0; half < 2; half++) {
            const int kk = 2*w + half;
            const float4* vbase = reinterpret_cast<const float4*>(gv + rowbase[kk]);
            const int jbase = kk*Ln;
#pragma unroll 3
            for (int l = 0; l < Ln; l++) {
                float p = prow[jbase + l];
                u64 pp = pack2(p, p);
                const float4* src = vbase + l*4;
                F4U2 v0, v1, v2, v3;
                v0.f = src[0]; v1.f = src[1]; v2.f = src[2]; v3.f = src[3];
                acc[0] = fma2(pp, v0.u[0], acc[0]); acc[1] = fma2(pp, v0.u[1], acc[1]);
                acc[2] = fma2(pp, v1.u[0], acc[2]); acc[3] = fma2(pp, v1.u[1], acc[3]);
                acc[4] = fma2(pp, v2.u[0], acc[4]); acc[5] = fma2(pp, v2.u[1], acc[5]);
                acc[6] = fma2(pp, v3.u[0], acc[6]); acc[7] = fma2(pp, v3.u[1], acc[7]);
            }
        }
    }
    __syncthreads();   // sc reads done; region reusable for partials
    if (lane < Ln) {
        float av[16];
#pragma unroll
        for (int d = 0; d < 8; d++) unpack2(acc[d], av[2*d], av[2*d+1]);
        float4* dst = reinterpret_cast<float4*>(sc + w*480 + lane*HDn);
#pragma unroll
        for (int c = 0; c < 4; c++)
            dst[c] = make_float4(av[c*4+0], av[c*4+1], av[c*4+2], av[c*4+3]);
    }
    __syncthreads();

    // reduce 8 partials, write ctx HEAD-MAJOR (contiguous 480 floats per CTA)
    float* ctxbase = ctx_out + (size_t)(ba*Hn + h)*HSTRIDE;
    for (int e = tid; e < Ln*HDn; e += 256) {
        float s = 0.f;
#pragma unroll
        for (int ww = 0; ww < 8; ww++) s += sc[ww*480 + e];
        ctxbase[e] = s;
    }
}

// ---------------------------------------------------------------------------
extern "C" void kernel_launch(void* const* d_in, const int* in_sizes, int n_in,
                              void* d_out, int out_size)
{
    const float* ff   = (const float*)d_in[0];
    const float* gb   = (const float*)d_in[1];
    const float* Wq   = (const float*)d_in[2];
    const float* bq   = (const float*)d_in[3];
    const float* Wk   = (const float*)d_in[4];
    const float* bk   = (const float*)d_in[5];
    const float* Wv   = (const float*)d_in[6];
    const float* bv   = (const float*)d_in[7];
    const float* Wo   = (const float*)d_in[8];
    const float* bo   = (const float*)d_in[9];
    const int*   nidx = (const int*)d_in[10];
    const void*  nmask = (const void*)d_in[11];

    float* out  = (float*)d_out;
    float* attn = out + (size_t)Bn*An*Ln*Mn;

    float *pq, *pk, *pv, *pctx;
    cudaGetSymbolAddress((void**)&pq,  g_q);
    cudaGetSymbolAddress((void**)&pk,  g_k);
    cudaGetSymbolAddress((void**)&pv,  g_v);
    cudaGetSymbolAddress((void**)&pctx, g_ctx);

    const int gemm_smem = 64*129*4;                        // 33024 B
    const int attn_smem = (Ln*HDn + Ln*SCP) * 4;           // 59640 B
    cudaFuncSetAttribute(gemm_qkv_kernel, cudaFuncAttributeMaxDynamicSharedMemorySize, gemm_smem);
    cudaFuncSetAttribute(gemm_out_kernel, cudaFuncAttributeMaxDynamicSharedMemorySize, gemm_smem);
    cudaFuncSetAttribute(attn_kernel,     cudaFuncAttributeMaxDynamicSharedMemorySize, attn_smem);

    // launch #1: mask dtype detection
    detect_mask_kernel<<<1, 256>>>((const unsigned int*)nmask);

    // launch #2: fused QKV projections (head-major outputs), 720 CTAs x 512 thr
    dim3 gqkv(NROWS/64, 3);
    gemm_qkv_kernel<<<gqkv, 512, gemm_smem>>>(ff, Wq, bq, pq, Wk, bk, pk, Wv, bv, pv);

    // launch #3: alignment noop (profiled launch is #4 — keep attn there)
    noop_kernel<<<1, 32>>>();

    // launch #4: attention (4096 CTAs x 256 threads) — R10 config
    attn_kernel<<<Bn*An*Hn, 256, attn_smem>>>(pq, pk, pv, gb, nidx, nmask, attn, pctx);

    // launch #5: output projection (240 CTAs x 512 thr)
    gemm_out_kernel<<<NROWS/64, 512, gemm_smem>>>(pctx, Wo, bo, out);
}

// round 13
// speedup vs baseline: 1.7284x; 1.5551x over previous
#include <cuda_runtime.h>
#include <cuda_bf16.h>
#include <math_constants.h>

// Problem dims
#define Bn   8
#define An   64
#define Ln   30
#define Dn   128
#define Kn   16
#define Mn   128
#define Hn   8
#define HDn  16
#define NROWS (Bn*An*Ln)           // 15360
#define JTOT (Kn*Ln)               // 480
#define SCP  484                   // padded score stride (484 mod 32 = 4: mma A-frags conflict-free)
#define SCALE 0.25f
#define HSTRIDE 480                // floats per (ba,h) block in head-major layout
#define BASTRIDE 3840              // floats per ba block (8 heads)

// ---- packed f32x2 helpers (Blackwell FFMA2 path) ---------------------------
typedef unsigned long long u64;
typedef unsigned int u32;
union F4U2 { float4 f; u64 u[2]; };

__device__ __forceinline__ u64 pack2(float lo, float hi) {
    u64 r; asm("mov.b64 %0, {%1,%2};" : "=l"(r) : "f"(lo), "f"(hi)); return r;
}
__device__ __forceinline__ void unpack2(u64 v, float& lo, float& hi) {
    asm("mov.b64 {%0,%1}, %2;" : "=f"(lo), "=f"(hi) : "l"(v));
}
__device__ __forceinline__ u64 fma2(u64 a, u64 b, u64 c) {
    u64 d; asm("fma.rn.f32x2 %0, %1, %2, %3;" : "=l"(d) : "l"(a), "l"(b), "l"(c)); return d;
}
__device__ __forceinline__ u32 to_tf32(float x) {
    u32 r; asm("cvt.rna.tf32.f32 %0, %1;" : "=r"(r) : "f"(x)); return r;
}
__device__ __forceinline__ void mma_tf32(float c[4], const u32 a[4], const u32 b[2]) {
    asm volatile(
        "mma.sync.aligned.m16n8k8.row.col.f32.tf32.tf32.f32 "
        "{%0,%1,%2,%3}, {%4,%5,%6,%7}, {%8,%9}, {%0,%1,%2,%3};"
        : "+f"(c[0]), "+f"(c[1]), "+f"(c[2]), "+f"(c[3])
        : "r"(a[0]), "r"(a[1]), "r"(a[2]), "r"(a[3]), "r"(b[0]), "r"(b[1]));
}

// Scratch (device globals; no allocation allowed)
// Q/K/V/ctx stored HEAD-MAJOR: [ba(512)][h(8)][l(30)][hd(16)]
__device__ float g_q[NROWS*Mn];
__device__ float g_k[NROWS*Mn];
__device__ float g_v[NROWS*Mn];
__device__ float g_ctx[NROWS*Mn];
__device__ int   g_mask_mode;      // 0 = u8/bool, 1 = int32, 2 = float32

// ---------------------------------------------------------------------------
__global__ void __launch_bounds__(256) detect_mask_kernel(const unsigned int* __restrict__ m)
{
    __shared__ int s_f32, s_hi;
    if (threadIdx.x == 0) { s_f32 = 0; s_hi = 0; }
    __syncthreads();
    int f32 = 0, hi = 0;
#pragma unroll
    for (int i = 0; i < 8; i++) {
        unsigned int w = m[threadIdx.x + 256*i];
        f32 |= (w == 0x3f800000u);
        hi  |= ((w & 0xFFFFFF00u) != 0u);
    }
    if (f32) s_f32 = 1;
    if (hi)  s_hi  = 1;
    __syncthreads();
    if (threadIdx.x == 0)
        g_mask_mode = s_f32 ? 2 : (s_hi ? 0 : 1);
}

__global__ void noop_kernel() {}

// ---------------------------------------------------------------------------
// GEMM core (R10 config): 64x128 tile, 256 threads, thread 4 rows x 8 cols.
// X staged in smem (33KB); W via coalesced LDG.
// ---------------------------------------------------------------------------
__device__ __forceinline__ void gemm_compute(
    const float* __restrict__ W, const float* Xs, int tid, u64 acc[4][4])
{
    const int tx = tid & 15;
    const int ty = tid >> 4;
#pragma unroll
    for (int i = 0; i < 4; i++)
#pragma unroll
        for (int j = 0; j < 4; j++) acc[i][j] = 0ULL;

    const float4* Wg = reinterpret_cast<const float4*>(W);
#pragma unroll 8
    for (int k = 0; k < 128; k++) {
        u64 aa[4];
#pragma unroll
        for (int i = 0; i < 4; i++) {
            float a = Xs[(ty + 16*i)*129 + k];
            aa[i] = pack2(a, a);
        }
        F4U2 b0, b1;
        b0.f = __ldg(&Wg[k*32 + tx*2 + 0]);
        b1.f = __ldg(&Wg[k*32 + tx*2 + 1]);
        u64 bb[4] = {b0.u[0], b0.u[1], b1.u[0], b1.u[1]};
#pragma unroll
        for (int i = 0; i < 4; i++)
#pragma unroll
            for (int j = 0; j < 4; j++) acc[i][j] = fma2(aa[i], bb[j], acc[i][j]);
    }
}

// QKV GEMM: X = future_feat (row-major [15360,128]); writes HEAD-MAJOR.
__global__ void __launch_bounds__(256, 3) gemm_qkv_kernel(
    const float* __restrict__ X,
    const float* __restrict__ Wq, const float* __restrict__ bq, float* __restrict__ Cq,
    const float* __restrict__ Wk, const float* __restrict__ bk, float* __restrict__ Ck,
    const float* __restrict__ Wv, const float* __restrict__ bv, float* __restrict__ Cv)
{
    const float* W; const float* bias; float* C;
    if (blockIdx.y == 0)      { W = Wq; bias = bq; C = Cq; }
    else if (blockIdx.y == 1) { W = Wk; bias = bk; C = Ck; }
    else                      { W = Wv; bias = bv; C = Cv; }

    extern __shared__ float sm[];
    float* Xs = sm;                 // 64 x 129
    const int tid  = threadIdx.x;
    const int row0 = blockIdx.x * 64;

    const float4* Xg = reinterpret_cast<const float4*>(X + (size_t)row0 * 128);
#pragma unroll
    for (int i = 0; i < 8; i++) {
        int idx = tid + 256*i;
        float4 v = Xg[idx];
        int r = idx >> 5;
        int c = (idx & 31) * 4;
        Xs[r*129 + c + 0] = v.x;
        Xs[r*129 + c + 1] = v.y;
        Xs[r*129 + c + 2] = v.z;
        Xs[r*129 + c + 3] = v.w;
    }
    __syncthreads();

    u64 acc[4][4];
    gemm_compute(W, Xs, tid, acc);

    const int tx = tid & 15;
    const int ty = tid >> 4;
    const float4* bias4 = reinterpret_cast<const float4*>(bias);
    float4 bb0 = bias4[tx*2 + 0];
    float4 bb1 = bias4[tx*2 + 1];
    float bb[8] = {bb0.x, bb0.y, bb0.z, bb0.w, bb1.x, bb1.y, bb1.z, bb1.w};
    const int h   = tx >> 1;
    const int hd0 = (tx & 1) * 8;
#pragma unroll
    for (int i = 0; i < 4; i++) {
        int r  = row0 + ty + 16*i;      // global row = ba*30 + l
        int ba = r / Ln;
        int l  = r - ba*Ln;
        float av[8];
#pragma unroll
        for (int j = 0; j < 4; j++) unpack2(acc[i][j], av[j*2], av[j*2+1]);
        float4* dst = reinterpret_cast<float4*>(C + (size_t)ba*BASTRIDE + h*HSTRIDE + l*HDn + hd0);
        dst[0] = make_float4(av[0]+bb[0], av[1]+bb[1], av[2]+bb[2], av[3]+bb[3]);
        dst[1] = make_float4(av[4]+bb[4], av[5]+bb[5], av[6]+bb[6], av[7]+bb[7]);
    }
}

// Output GEMM: X = ctx in HEAD-MAJOR; gathers into smem; writes row-major out.
__global__ void __launch_bounds__(256, 3) gemm_out_kernel(
    const float* __restrict__ Xhm, const float* __restrict__ W,
    const float* __restrict__ bias, float* __restrict__ C)
{
    extern __shared__ float sm[];
    float* Xs = sm;                 // 64 x 129
    const int tid  = threadIdx.x;
    const int row0 = blockIdx.x * 64;

#pragma unroll
    for (int i = 0; i < 8; i++) {
        int idx = tid + 256*i;
        int r  = idx >> 5;
        int c4 = idx & 31;
        int g  = row0 + r;
        int ba = g / Ln;
        int l  = g - ba*Ln;
        int h  = c4 >> 2;
        int hd = (c4 & 3) * 4;
        float4 v = *reinterpret_cast<const float4*>(
            Xhm + (size_t)ba*BASTRIDE + h*HSTRIDE + l*HDn + hd);
        int c = c4 * 4;
        Xs[r*129 + c + 0] = v.x;
        Xs[r*129 + c + 1] = v.y;
        Xs[r*129 + c + 2] = v.z;
        Xs[r*129 + c + 3] = v.w;
    }
    __syncthreads();

    u64 acc[4][4];
    gemm_compute(W, Xs, tid, acc);

    const int tx = tid & 15;
    const int ty = tid >> 4;
    const float4* bias4 = reinterpret_cast<const float4*>(bias);
    float4 bb0 = bias4[tx*2 + 0];
    float4 bb1 = bias4[tx*2 + 1];
    float bb[8] = {bb0.x, bb0.y, bb0.z, bb0.w, bb1.x, bb1.y, bb1.z, bb1.w};
#pragma unroll
    for (int i = 0; i < 4; i++) {
        int r = row0 + ty + 16*i;
        float av[8];
#pragma unroll
        for (int j = 0; j < 4; j++) unpack2(acc[i][j], av[j*2], av[j*2+1]);
        float4* dst = reinterpret_cast<float4*>(C + (size_t)r*128 + tx*8);
        dst[0] = make_float4(av[0]+bb[0], av[1]+bb[1], av[2]+bb[2], av[3]+bb[3]);
        dst[1] = make_float4(av[4]+bb[4], av[5]+bb[5], av[6]+bb[6], av[7]+bb[7]);
    }
}

// ---------------------------------------------------------------------------
// Attention: 256-thread CTA per (b,a,h); 3 CTAs/SM. Head-major Q/K/V.
// Scores + softmax scalar fp32 (exact). P@V via tensor cores (tf32 mma).
// smem: qs[480] | sc[32*484] = 63872 B
// ---------------------------------------------------------------------------
__global__ void __launch_bounds__(256, 3) attn_kernel(
    const float* __restrict__ gq, const float* __restrict__ gk,
    const float* __restrict__ gv, const float* __restrict__ geom_bias,
    const int* __restrict__ nidx, const void* __restrict__ nmask,
    float* __restrict__ attn_out, float* __restrict__ ctx_out)
{
    const int bid = blockIdx.x;
    const int h  = bid & 7;
    const int a  = (bid >> 3) & 63;
    const int b  = bid >> 9;
    const int ba = b*An + a;
    const int tid = threadIdx.x;

    extern __shared__ float sm[];
    float* qs = sm;                    // 480 floats
    float* sc = qs + Ln*HDn;           // 32*484 (scores rows 0-29, zero rows 30-31)

    __shared__ int   rowbase[Kn];
    __shared__ float biasS[Kn];
    __shared__ int   maskS[Kn];

    if (tid < Kn) {
        int n = nidx[ba*Kn + tid];
        rowbase[tid] = ((b*An + n)*Hn + h) * HSTRIDE;
        biasS[tid]   = geom_bias[ba*Kn + tid];
        int mode = g_mask_mode;
        bool mv;
        if (mode == 0)      mv = ((const unsigned char*)nmask)[ba*Kn + tid] != 0;
        else if (mode == 1) mv = ((const int*)nmask)[ba*Kn + tid] != 0;
        else                mv = ((const float*)nmask)[ba*Kn + tid] != 0.0f;
        maskS[tid] = mv ? 1 : 0;
    }
    // q head slice: contiguous 480 floats = 120 float4
    if (tid < Ln*4) {
        const float4* qbase = reinterpret_cast<const float4*>(gq + (size_t)(ba*Hn + h)*HSTRIDE);
        reinterpret_cast<float4*>(qs)[tid] = qbase[tid];
    }
    // zero the mma padding rows 30,31 of sc (968 floats)
    for (int i = tid; i < 2*SCP; i += 256) sc[30*SCP + i] = 0.f;
    __syncthreads();   // rowbase + qs + pad rows ready

    // K rows straight from global into PACKED registers
    const int j0 = tid;
    const int j1 = tid + 256;
    const bool hasJ1 = (tid < JTOT - 256);   // tid < 224
    const int kk0 = j0 / Ln;
    const int l0  = j0 - kk0*Ln;
    const int kk1 = j1 / Ln;
    const int l1  = j1 - kk1*Ln;
    u64 k0[8], k1[8];
    {
        const float4* src0 = reinterpret_cast<const float4*>(gk + rowbase[kk0] + l0*HDn);
        F4U2 t;
#pragma unroll
        for (int c = 0; c < 4; c++) {
            t.f = src0[c];
            k0[c*2+0] = t.u[0]; k0[c*2+1] = t.u[1];
        }
        if (hasJ1) {
            const float4* src1 = reinterpret_cast<const float4*>(gk + rowbase[kk1] + l1*HDn);
#pragma unroll
            for (int c = 0; c < 4; c++) {
                t.f = src1[c];
                k1[c*2+0] = t.u[0]; k1[c*2+1] = t.u[1];
            }
        }
    }
    const float bias0 = biasS[kk0];
    const bool  m0 = maskS[kk0] != 0;
    const float bias1 = hasJ1 ? biasS[kk1] : 0.f;
    const bool  m1 = hasJ1 ? (maskS[kk1] != 0) : false;

    // scores from packed register K (exact fp32)
    const float NEGINF = -CUDART_INF_F;
    const float4* qs4 = reinterpret_cast<const float4*>(qs);
#pragma unroll 1
    for (int qp = 0; qp < Ln/2; qp++) {
        int q0 = qp * 2;
        u64 qa[8], qb[8];
        {
            F4U2 t;
#pragma unroll
            for (int c = 0; c < 4; c++) {
                t.f = qs4[q0*4 + c];
                qa[c*2+0] = t.u[0]; qa[c*2+1] = t.u[1];
            }
#pragma unroll
            for (int c = 0; c < 4; c++) {
                t.f = qs4[(q0+1)*4 + c];
                qb[c*2+0] = t.u[0]; qb[c*2+1] = t.u[1];
            }
        }
        u64 p00 = 0ULL, p10 = 0ULL, p01 = 0ULL, p11 = 0ULL;
#pragma unroll
        for (int d = 0; d < 8; d++) {
            p00 = fma2(qa[d], k0[d], p00);
            p10 = fma2(qb[d], k0[d], p10);
        }
        if (hasJ1) {
#pragma unroll
            for (int d = 0; d < 8; d++) {
                p01 = fma2(qa[d], k1[d], p01);
                p11 = fma2(qb[d], k1[d], p11);
            }
        }
        float lo, hi;
        unpack2(p00, lo, hi); float s00 = lo + hi;
        unpack2(p10, lo, hi); float s10 = lo + hi;
        sc[q0*SCP + j0]     = m0 ? fmaf(s00, SCALE, bias0) : NEGINF;
        sc[(q0+1)*SCP + j0] = m0 ? fmaf(s10, SCALE, bias0) : NEGINF;
        if (hasJ1) {
            unpack2(p01, lo, hi); float s01 = lo + hi;
            unpack2(p11, lo, hi); float s11 = lo + hi;
            sc[q0*SCP + j1]     = m1 ? fmaf(s01, SCALE, bias1) : NEGINF;
            sc[(q0+1)*SCP + j1] = m1 ? fmaf(s11, SCALE, bias1) : NEGINF;
        }
    }
    __syncthreads();

    // softmax: one warp per row, 15 elements per lane held in registers (exact)
    const int warp = tid >> 5;
    const int lane = tid & 31;
    for (int q = warp; q < Ln; q += 8) {
        float* row = sc + q*SCP;
        float* arow = attn_out + ((size_t)(ba*Hn + h)*Ln + q) * JTOT;
        float p[15];
#pragma unroll
        for (int i = 0; i < 15; i++) p[i] = row[i*32 + lane];
        float m = p[0];
#pragma unroll
        for (int i = 1; i < 15; i++) m = fmaxf(m, p[i]);
#pragma unroll
        for (int off = 16; off; off >>= 1) m = fmaxf(m, __shfl_xor_sync(0xffffffffu, m, off));
        if (m == NEGINF) {
#pragma unroll
            for (int i = 0; i < 15; i++) { row[i*32 + lane] = 0.f; arow[i*32 + lane] = 0.f; }
        } else {
            float s = 0.f;
#pragma unroll
            for (int i = 0; i < 15; i++) { p[i] = __expf(p[i] - m); s += p[i]; }
#pragma unroll
            for (int off = 16; off; off >>= 1) s += __shfl_xor_sync(0xffffffffu, s, off);
            float inv = 1.f / s;
#pragma unroll
            for (int i = 0; i < 15; i++) {
                float v = p[i] * inv;
                row[i*32 + lane] = v;
                arow[i*32 + lane] = v;
            }
        }
    }
    __syncthreads();

    // ------------------------------------------------------------------
    // P @ V via tensor cores: ctx[32x16] = P[32x480] @ V[480x16] (tf32).
    // 2 M-tiles x 2 N-tiles x 60 k-tiles; warp w owns k-tiles {w, w+8, ...}.
    // A from sc (stride 484: conflict-free), B straight from global V.
    // ------------------------------------------------------------------
    float cfr[4][4];   // [mt*2+nt][4]
#pragma unroll
    for (int i = 0; i < 4; i++)
#pragma unroll
        for (int j = 0; j < 4; j++) cfr[i][j] = 0.f;

    const int r  = lane >> 2;      // 0..7
    const int cc = lane & 3;       // 0..3
#pragma unroll 1
    for (int t = warp; t < 60; t += 8) {
        // A fragments (P): a0=A[r][c], a1=A[r+8][c], a2=A[r][c+4], a3=A[r+8][c+4]
        u32 A[2][4];
#pragma unroll
        for (int mt = 0; mt < 2; mt++) {
            const float* base  = sc + (mt*16 + r)*SCP + t*8 + cc;
            const float* base8 = base + 8*SCP;
            A[mt][0] = to_tf32(base[0]);
            A[mt][1] = to_tf32(base8[0]);
            A[mt][2] = to_tf32(base[4]);
            A[mt][3] = to_tf32(base8[4]);
        }
        // B fragments (V) from global: b0=B[k=cc][n], b1=B[k=cc+4][n], n = r
        int jA = t*8 + cc;
        int jB = jA + 4;
        int kkA = jA / Ln, lA = jA - kkA*Ln;
        int kkB = jB / Ln, lB = jB - kkB*Ln;
        const float* va = gv + rowbase[kkA] + lA*HDn;
        const float* vb = gv + rowbase[kkB] + lB*HDn;
        u32 B[2][2];
#pragma unroll
        for (int nt = 0; nt < 2; nt++) {
            B[nt][0] = to_tf32(va[nt*8 + r]);
            B[nt][1] = to_tf32(vb[nt*8 + r]);
        }
#pragma unroll
        for (int mt = 0; mt < 2; mt++)
#pragma unroll
            for (int nt = 0; nt < 2; nt++)
                mma_tf32(cfr[mt*2+nt], A[mt], B[nt]);
    }
    __syncthreads();   // all A-frag reads of sc done

    // write per-warp partials into sc region: [w][row(32)][d(16)] blocks
    {
        float* part = sc + warp*512;
#pragma unroll
        for (int mt = 0; mt < 2; mt++)
#pragma unroll
            for (int nt = 0; nt < 2; nt++) {
                int row = mt*16 + r;
                int col = nt*8 + cc*2;
                float* d0 = part + row*16 + col;
                d0[0]      = cfr[mt*2+nt][0];
                d0[1]      = cfr[mt*2+nt][1];
                d0[8*16]   = cfr[mt*2+nt][2];
                d0[8*16+1] = cfr[mt*2+nt][3];
            }
    }
    __syncthreads();

    // reduce 8 partials, write ctx HEAD-MAJOR (rows 0..29 only = 480 elems)
    float* ctxbase = ctx_out + (size_t)(ba*Hn + h)*HSTRIDE;
    for (int e = tid; e < Ln*HDn; e += 256) {
        float s = 0.f;
#pragma unroll
        for (int ww = 0; ww < 8; ww++) s += sc[ww*512 + e];
        ctxbase[e] = s;
    }
}

// ---------------------------------------------------------------------------
extern "C" void kernel_launch(void* const* d_in, const int* in_sizes, int n_in,
                              void* d_out, int out_size)
{
    const float* ff   = (const float*)d_in[0];
    const float* gb   = (const float*)d_in[1];
    const float* Wq   = (const float*)d_in[2];
    const float* bq   = (const float*)d_in[3];
    const float* Wk   = (const float*)d_in[4];
    const float* bk   = (const float*)d_in[5];
    const float* Wv   = (const float*)d_in[6];
    const float* bv   = (const float*)d_in[7];
    const float* Wo   = (const float*)d_in[8];
    const float* bo   = (const float*)d_in[9];
    const int*   nidx = (const int*)d_in[10];
    const void*  nmask = (const void*)d_in[11];

    float* out  = (float*)d_out;
    float* attn = out + (size_t)Bn*An*Ln*Mn;

    float *pq, *pk, *pv, *pctx;
    cudaGetSymbolAddress((void**)&pq,  g_q);
    cudaGetSymbolAddress((void**)&pk,  g_k);
    cudaGetSymbolAddress((void**)&pv,  g_v);
    cudaGetSymbolAddress((void**)&pctx, g_ctx);

    const int gemm_smem = 64*129*4;                        // 33024 B
    const int attn_smem = (Ln*HDn + 32*SCP) * 4;           // 63872 B
    cudaFuncSetAttribute(gemm_qkv_kernel, cudaFuncAttributeMaxDynamicSharedMemorySize, gemm_smem);
    cudaFuncSetAttribute(gemm_out_kernel, cudaFuncAttributeMaxDynamicSharedMemorySize, gemm_smem);
    cudaFuncSetAttribute(attn_kernel,     cudaFuncAttributeMaxDynamicSharedMemorySize, attn_smem);

    // launch #1: mask dtype detection
    detect_mask_kernel<<<1, 256>>>((const unsigned int*)nmask);

    // launch #2: fused QKV projections (head-major outputs), 720 CTAs x 256 thr
    dim3 gqkv(NROWS/64, 3);
    gemm_qkv_kernel<<<gqkv, 256, gemm_smem>>>(ff, Wq, bq, pq, Wk, bk, pk, Wv, bv, pv);

    // launch #3: alignment noop (profiled launch is #4 — keep attn there)
    noop_kernel<<<1, 32>>>();

    // launch #4: attention (4096 CTAs x 256 threads)
    attn_kernel<<<Bn*An*Hn, 256, attn_smem>>>(pq, pk, pv, gb, nidx, nmask, attn, pctx);

    // launch #5: output projection (240 CTAs x 256 thr)
    gemm_out_kernel<<<NROWS/64, 256, gemm_smem>>>(pctx, Wo, bo, out);
}